// round 16
// baseline (speedup 1.0000x reference)
#include <cuda_runtime.h>
#include <stdint.h>

#define NN     4096
#define FIN    256
#define NHEADS 4
#define FOUT_  64
#define CTOT   256
#define MI     32            // rows per attention CTA
#define SJ     2             // j-range splits
#define KJ     (NN / SJ)     // 2048 j per CTA
#define TILE   32
#define NTILES (KJ / TILE)   // 64
#define HPAD   264           // h_s row stride (mod 32 = 8 -> conflict-free B LDS)

// Scratch
__device__ float  g_h [NN * CTOT];            // tf32-rounded h = x@W
__device__ float  g_e1[NN * NHEADS];
__device__ float  g_e2[NN * NHEADS];
__device__ float  g_gmax[NHEADS];
__device__ float  g_v1[FIN * NHEADS];         // W @ a1  (per head)
__device__ float  g_v2[FIN * NHEADS];         // W @ a2
__device__ float2 g_aa[NN * NHEADS];          // {exp(e1-m), exp(0.2 e1-m)}
__device__ float2 g_bb[NN * NHEADS];          // {exp(e2),   exp(0.2 e2)}
__device__ float  g_part [SJ][NN][CTOT];      // numerator partials
__device__ float  g_zpart[SJ][NN][NHEADS];    // Z partials

__device__ __forceinline__ float lrelu(float s) { return fmaxf(s, 0.2f * s); }

__device__ __forceinline__ unsigned to_tf32(float x)
{
    unsigned u;
    asm("cvt.rna.tf32.f32 %0, %1;" : "=r"(u) : "f"(x));
    return u;
}
__device__ __forceinline__ float tf32f(float x)
{
    return __uint_as_float(to_tf32(x));
}

__device__ __forceinline__ void mma_tf32(float* c, const unsigned* a,
                                         unsigned b0, unsigned b1)
{
    asm("mma.sync.aligned.m16n8k8.row.col.f32.tf32.tf32.f32 "
        "{%0,%1,%2,%3}, {%4,%5,%6,%7}, {%8,%9}, {%0,%1,%2,%3};"
        : "+f"(c[0]), "+f"(c[1]), "+f"(c[2]), "+f"(c[3])
        : "r"(a[0]), "r"(a[1]), "r"(a[2]), "r"(a[3]), "r"(b0), "r"(b1));
}

__device__ __forceinline__ void cp_async16(uint32_t smem_addr, const void* gptr)
{
    asm volatile("cp.async.cg.shared.global [%0], [%1], 16;"
                 :: "r"(smem_addr), "l"(gptr));
}

// ---------------------------------------------------------------------------
// Kernel 0: v1 = W @ a1, v2 = W @ a2 per head (exact fp32).
// ---------------------------------------------------------------------------
__global__ __launch_bounds__(256) void k_wa(const float* __restrict__ W,
                                            const float* __restrict__ a)
{
    const int k = threadIdx.x;           // 0..255
    float s1[4] = {0.f, 0.f, 0.f, 0.f};
    float s2[4] = {0.f, 0.f, 0.f, 0.f};
#pragma unroll 4
    for (int f = 0; f < 64; f++) {
        const float a1 = a[f];
        const float a2 = a[64 + f];
#pragma unroll
        for (int h = 0; h < 4; h++) {
            const float wv = W[k * CTOT + h * 64 + f];
            s1[h] += wv * a1;
            s2[h] += wv * a2;
        }
    }
#pragma unroll
    for (int h = 0; h < 4; h++) {
        g_v1[k * 4 + h] = s1[h];
        g_v2[k * 4 + h] = s2[h];
    }
}

// ---------------------------------------------------------------------------
// Kernel 0b: e1 = x @ v1, e2 = x @ v2 (exact fp32; warp per row).
// ---------------------------------------------------------------------------
__global__ __launch_bounds__(256) void k_e(const float* __restrict__ x)
{
    __shared__ float4 v1s[FIN], v2s[FIN];
    const int t = threadIdx.x;
    v1s[t] = *(const float4*)&g_v1[t * 4];
    v2s[t] = *(const float4*)&g_v2[t * 4];
    __syncthreads();

    const int lane = t & 31;
    const int w    = t >> 5;
    const int row  = blockIdx.x * 8 + w;

    float4 p1 = make_float4(0.f, 0.f, 0.f, 0.f);
    float4 p2 = make_float4(0.f, 0.f, 0.f, 0.f);
#pragma unroll
    for (int q = 0; q < 8; q++) {
        const int k = q * 32 + lane;
        const float xv = x[(size_t)row * FIN + k];
        const float4 v1 = v1s[k];
        const float4 v2 = v2s[k];
        p1.x += xv * v1.x; p1.y += xv * v1.y; p1.z += xv * v1.z; p1.w += xv * v1.w;
        p2.x += xv * v2.x; p2.y += xv * v2.y; p2.z += xv * v2.z; p2.w += xv * v2.w;
    }
#pragma unroll
    for (int o = 16; o; o >>= 1) {
        p1.x += __shfl_xor_sync(0xffffffffu, p1.x, o);
        p1.y += __shfl_xor_sync(0xffffffffu, p1.y, o);
        p1.z += __shfl_xor_sync(0xffffffffu, p1.z, o);
        p1.w += __shfl_xor_sync(0xffffffffu, p1.w, o);
        p2.x += __shfl_xor_sync(0xffffffffu, p2.x, o);
        p2.y += __shfl_xor_sync(0xffffffffu, p2.y, o);
        p2.z += __shfl_xor_sync(0xffffffffu, p2.z, o);
        p2.w += __shfl_xor_sync(0xffffffffu, p2.w, o);
    }
    if (lane == 0) {
        *(float4*)&g_e1[row * 4] = p1;
        *(float4*)&g_e2[row * 4] = p2;
    }
}

// ---------------------------------------------------------------------------
// Kernel 1: h = x @ W via tf32 mma.sync. CTA: 32 rows x 256 cols, 8 warps
// (2 rowgroups x 4 colgroups). Inputs tf32-rounded at staging.
// ---------------------------------------------------------------------------
__global__ __launch_bounds__(256) void k_proj(const float* __restrict__ x,
                                              const float* __restrict__ W)
{
    __shared__ float xs[32][36];
    __shared__ float Ws[32][264];

    const int t    = threadIdx.x;
    const int lane = t & 31;
    const int w    = t >> 5;
    const int rg   = w & 1;
    const int cg   = w >> 1;
    const int r0   = lane >> 2;
    const int c0   = lane & 3;
    const int n0   = blockIdx.x * 32;

    float acc[8][4];
#pragma unroll
    for (int nt = 0; nt < 8; nt++)
#pragma unroll
        for (int q = 0; q < 4; q++) acc[nt][q] = 0.f;

    for (int kt = 0; kt < FIN / 32; kt++) {
        const int k0 = kt * 32;
        __syncthreads();
        // stage x tile 32x32 (tf32-rounded): 256 float4, 1/thread
        {
            const int row = t >> 3, k4 = t & 7;
            float4 v = *(const float4*)&x[(size_t)(n0 + row) * FIN + k0 + k4 * 4];
            v.x = tf32f(v.x); v.y = tf32f(v.y); v.z = tf32f(v.z); v.w = tf32f(v.w);
            *(float4*)&xs[row][k4 * 4] = v;
        }
        // stage W tile 32x256 (tf32-rounded): 2048 float4, 8/thread
#pragma unroll
        for (int q = 0; q < 8; q++) {
            const int f = t + q * 256;
            const int k = f >> 6, c4 = f & 63;
            float4 v = *(const float4*)&W[(size_t)(k0 + k) * CTOT + c4 * 4];
            v.x = tf32f(v.x); v.y = tf32f(v.y); v.z = tf32f(v.z); v.w = tf32f(v.w);
            *(float4*)&Ws[k][c4 * 4] = v;
        }
        __syncthreads();

#pragma unroll
        for (int kc = 0; kc < 4; kc++) {
            unsigned afr[4];
            afr[0] = __float_as_uint(xs[rg * 16 + r0][kc * 8 + c0]);
            afr[1] = __float_as_uint(xs[rg * 16 + r0 + 8][kc * 8 + c0]);
            afr[2] = __float_as_uint(xs[rg * 16 + r0][kc * 8 + c0 + 4]);
            afr[3] = __float_as_uint(xs[rg * 16 + r0 + 8][kc * 8 + c0 + 4]);
#pragma unroll
            for (int nt = 0; nt < 8; nt++) {
                const int col = cg * 64 + nt * 8 + r0;
                const unsigned b0 = __float_as_uint(Ws[kc * 8 + c0][col]);
                const unsigned b1 = __float_as_uint(Ws[kc * 8 + c0 + 4][col]);
                mma_tf32(acc[nt], afr, b0, b1);
            }
        }
    }

    // epilogue: store tf32-rounded h
    const int node = n0 + rg * 16 + r0;
#pragma unroll
    for (int nt = 0; nt < 8; nt++) {
        const int col = cg * 64 + nt * 8 + 2 * c0;
        *(float2*)&g_h[(size_t)node * CTOT + col] =
            make_float2(tf32f(acc[nt][0]), tf32f(acc[nt][1]));
        *(float2*)&g_h[(size_t)(node + 8) * CTOT + col] =
            make_float2(tf32f(acc[nt][2]), tf32f(acc[nt][3]));
    }
}

// ---------------------------------------------------------------------------
// Kernel 1b: global max of e2 per head.
// ---------------------------------------------------------------------------
__global__ __launch_bounds__(256) void k_gmax()
{
    const int t = threadIdx.x;
    const int h = t & 3;
    float m = -1e30f;
    for (int n = t >> 2; n < NN; n += 64)
        m = fmaxf(m, g_e2[n * NHEADS + h]);
    __shared__ float sm[256];
    sm[t] = m;
    __syncthreads();
    for (int s = 128; s >= 4; s >>= 1) {
        if (t < s) sm[t] = fmaxf(sm[t], sm[t + s]);
        __syncthreads();
    }
    if (t < 4) g_gmax[t] = sm[t];
}

// ---------------------------------------------------------------------------
// Kernel 1c: factored softmax terms. m_i = lrelu(e1+gmax) >= masked row max.
// ---------------------------------------------------------------------------
__global__ __launch_bounds__(256) void k_prep()
{
    const int idx = blockIdx.x * 256 + threadIdx.x;   // node*NHEADS + head
    const int h   = idx & 3;
    const float e1 = g_e1[idx];
    const float e2 = g_e2[idx];
    const float gm = g_gmax[h];
    const float m  = lrelu(e1 + gm);
    g_aa[idx] = make_float2(__expf(e1 - m), __expf(0.2f * e1 - m));
    g_bb[idx] = make_float2(__expf(e2), __expf(0.2f * e2));
}

// ---------------------------------------------------------------------------
// Kernel 2: tensor-core masked softmax-aggregation, cp.async double-buffered.
//   CTA: 256 threads = 8 warps, MI=32 rows, KJ j's. 2 CTAs/SM.
//   Warp (rg = wid&1, hh = wid>>1): 16 rows, head hh.
// ---------------------------------------------------------------------------
__global__ __launch_bounds__(256, 2) void k_attn(const int* __restrict__ adj)
{
    extern __shared__ float smem[];
    float*    h_s0   = smem;                               // 2 x 32 x 264
    float2*   bb_s0  = (float2*)(smem + 2 * TILE * HPAD);  // 2 x 32 x 4
    unsigned* mask_s = (unsigned*)(bb_s0 + 2 * TILE * NHEADS);
    float*    zred   = (float*)(mask_s + MI);

    const int t    = threadIdx.x;
    const int lane = t & 31;
    const int wid  = t >> 5;
    const int rg   = wid & 1;
    const int hh   = wid >> 1;
    const int r0   = lane >> 2;
    const int c0   = lane & 3;

    const int row0 = (blockIdx.x >> 1) * MI;
    const int js   = blockIdx.x & 1;
    const int jb0  = js * KJ;

    const int rowA = row0 + rg * 16 + r0;
    const float2 aa0 = g_aa[(size_t)rowA * NHEADS + hh];
    const float2 aa1 = g_aa[(size_t)(rowA + 8) * NHEADS + hh];

    float acc[8][4];
#pragma unroll
    for (int n = 0; n < 8; n++)
#pragma unroll
        for (int q = 0; q < 4; q++) acc[n][q] = 0.f;
    float z0 = 0.f, z1 = 0.f;

    const uint32_t hbase   = (uint32_t)__cvta_generic_to_shared(h_s0);
    const uint32_t bbase   = (uint32_t)__cvta_generic_to_shared(bb_s0);
    const uint32_t hbuf_b  = TILE * HPAD * 4;
    const uint32_t bbbuf_b = TILE * NHEADS * 8;

    // stage tile `tl` into buffer p (one commit group per call)
    auto stage = [&](int tl, int p) {
        const int jb = jb0 + tl * TILE;
        const float* src = g_h + (size_t)jb * CTOT;
        const uint32_t hb = hbase + p * hbuf_b;
#pragma unroll
        for (int q = 0; q < 8; q++) {
            const int f = t + q * 256;            // float4 id 0..2047
            cp_async16(hb + (uint32_t)(((f >> 6) * HPAD + (f & 63) * 4) * 4),
                       src + f * 4);
        }
        if (t < 64)
            cp_async16(bbase + p * bbbuf_b + t * 16,
                       (const char*)(g_bb + (size_t)jb * NHEADS) + t * 16);
    };

    // adjacency prefetch: warp wid covers rows row0 + wid*4 .. +3
    const int mrow = row0 + wid * 4;
    int av[4];
#pragma unroll
    for (int rr = 0; rr < 4; rr++)
        av[rr] = adj[(size_t)(mrow + rr) * NN + jb0 + lane];

    stage(0, 0);
    asm volatile("cp.async.commit_group;");

    for (int tile = 0; tile < NTILES; tile++) {
        const int p = tile & 1;

        if (tile + 1 < NTILES) {
            stage(tile + 1, p ^ 1);
            asm volatile("cp.async.commit_group;");
            asm volatile("cp.async.wait_group 1;");
        } else {
            asm volatile("cp.async.wait_group 0;");
        }

        // masks for this tile + prefetch next adjacency
#pragma unroll
        for (int rr = 0; rr < 4; rr++) {
            unsigned m = __ballot_sync(0xffffffffu, av[rr] != 0);
            if (lane == 0) mask_s[wid * 4 + rr] = m;
        }
        if (tile + 1 < NTILES) {
            const int jbn = jb0 + (tile + 1) * TILE;
#pragma unroll
            for (int rr = 0; rr < 4; rr++)
                av[rr] = adj[(size_t)(mrow + rr) * NN + jbn + lane];
        }
        __syncthreads();

        const float*  hs = h_s0 + p * TILE * HPAD;
        const float2* bs = bb_s0 + p * TILE * NHEADS;
        const unsigned mw0 = mask_s[rg * 16 + r0];
        const unsigned mw1 = mask_s[rg * 16 + r0 + 8];

#pragma unroll
        for (int kc = 0; kc < 4; kc++) {
            const int jl0 = kc * 8 + c0;
            const int jl1 = jl0 + 4;
            const float2 bb0 = bs[jl0 * NHEADS + hh];
            const float2 bb1 = bs[jl1 * NHEADS + hh];

            float w0 = fmaxf(aa0.x * bb0.x, aa0.y * bb0.y);
            float w1 = fmaxf(aa1.x * bb0.x, aa1.y * bb0.y);
            float w2 = fmaxf(aa0.x * bb1.x, aa0.y * bb1.y);
            float w3 = fmaxf(aa1.x * bb1.x, aa1.y * bb1.y);
            if (!((mw0 >> jl0) & 1u)) w0 = 0.f;
            if (!((mw1 >> jl0) & 1u)) w1 = 0.f;
            if (!((mw0 >> jl1) & 1u)) w2 = 0.f;
            if (!((mw1 >> jl1) & 1u)) w3 = 0.f;
            z0 += w0 + w2;
            z1 += w1 + w3;

            unsigned afr[4];
            afr[0] = to_tf32(w0);
            afr[1] = to_tf32(w1);
            afr[2] = to_tf32(w2);
            afr[3] = to_tf32(w3);

#pragma unroll
            for (int nt = 0; nt < 8; nt++) {
                const int n0 = hh * 64 + nt * 8 + r0;
                const unsigned b0 = __float_as_uint(hs[jl0 * HPAD + n0]);
                const unsigned b1 = __float_as_uint(hs[jl1 * HPAD + n0]);
                mma_tf32(acc[nt], afr, b0, b1);
            }
        }
        __syncthreads();   // compute done before buffer p is restaged
    }

    // Z: reduce across the 4 lanes sharing a row
#pragma unroll
    for (int o = 1; o <= 2; o <<= 1) {
        z0 += __shfl_xor_sync(0xffffffffu, z0, o);
        z1 += __shfl_xor_sync(0xffffffffu, z1, o);
    }
    if (c0 == 0) {
        zred[(rg * 16 + r0) * NHEADS + hh]     = z0;
        zred[(rg * 16 + r0 + 8) * NHEADS + hh] = z1;
    }
    __syncthreads();
    if (t < MI * NHEADS)
        g_zpart[js][row0 + (t >> 2)][t & 3] = zred[t];

    // numerator partials straight from accumulators
#pragma unroll
    for (int nt = 0; nt < 8; nt++) {
        const int cb = hh * 64 + nt * 8 + 2 * c0;
        *(float2*)&g_part[js][rowA][cb]     = make_float2(acc[nt][0], acc[nt][1]);
        *(float2*)&g_part[js][rowA + 8][cb] = make_float2(acc[nt][2], acc[nt][3]);
    }
}

// ---------------------------------------------------------------------------
// Kernel 3: combine j-splits, normalize by Z, mean over heads.
// ---------------------------------------------------------------------------
__global__ __launch_bounds__(256) void k_final(float* __restrict__ out)
{
    const int idx = blockIdx.x * 256 + threadIdx.x;   // row*64 + f
    const int row = idx >> 6;
    const int f   = idx & 63;
    float o = 0.f;
#pragma unroll
    for (int h = 0; h < NHEADS; h++) {
        const float num = g_part[0][row][h * 64 + f] + g_part[1][row][h * 64 + f];
        const float zz  = g_zpart[0][row][h] + g_zpart[1][row][h];
        o += num / zz;
    }
    out[idx] = 0.25f * o;
}

// ---------------------------------------------------------------------------
extern "C" void kernel_launch(void* const* d_in, const int* in_sizes, int n_in,
                              void* d_out, int out_size)
{
    const float* x   = (const float*)d_in[0];   // 4096 x 256
    const int*   adj = (const int*)  d_in[1];   // 4096 x 4096
    const float* W   = (const float*)d_in[2];   // 256 x 256
    const float* a   = (const float*)d_in[3];   // 128 x 1
    float* out = (float*)d_out;                 // 4096 x 64

    (void)in_sizes; (void)n_in; (void)out_size;

    const int smem_attn = (2 * TILE * HPAD) * 4          // h_s
                        + (2 * TILE * NHEADS) * 8        // bb_s
                        + MI * 4                         // masks
                        + MI * NHEADS * 4;               // zred
    cudaFuncSetAttribute(k_attn, cudaFuncAttributeMaxDynamicSharedMemorySize,
                         smem_attn);

    k_wa<<<1, 256>>>(W, a);
    k_e<<<NN / 8, 256>>>(x);
    k_proj<<<NN / 32, 256>>>(x, W);
    k_gmax<<<1, 256>>>();
    k_prep<<<NN * NHEADS / 256, 256>>>();
    k_attn<<<(NN / MI) * SJ, 256, smem_attn>>>(adj);
    k_final<<<NN * FOUT_ / 256, 256>>>(out);
}